// round 7
// baseline (speedup 1.0000x reference)
#include <cuda_runtime.h>
#include <cuda_bf16.h>
#include <math.h>

#define BATCH 2
#define SEQ   4096
#define DM    512
#define ROWS  (BATCH*SEQ)   // 8192

typedef unsigned short u16;
typedef unsigned int   u32;

// ---------------------------------------------------------------------------
// Device scratch (allocation-free rule: __device__ globals)
// ---------------------------------------------------------------------------
__device__ u16 g_Qh[(size_t)ROWS*DM], g_Ql[(size_t)ROWS*DM];
__device__ u16 g_Kh[(size_t)ROWS*DM], g_Kl[(size_t)ROWS*DM];
__device__ u16 g_Vh[(size_t)ROWS*DM], g_Vl[(size_t)ROWS*DM];
__device__ u16 g_Wqh[DM*DM], g_Wql[DM*DM];
__device__ u16 g_Wkh[DM*DM], g_Wkl[DM*DM];
__device__ u16 g_Wvh[DM*DM], g_Wvl[DM*DM];
__device__ u16 g_qh[(size_t)ROWS*DM], g_ql[(size_t)ROWS*DM];
__device__ u16 g_kh[(size_t)ROWS*DM], g_kl[(size_t)ROWS*DM];
__device__ u16 g_vth[(size_t)BATCH*DM*SEQ], g_vtl[(size_t)BATCH*DM*SEQ];
__device__ float g_s[(size_t)BATCH*SEQ*SEQ];
__device__ u16 g_ah[(size_t)BATCH*SEQ*SEQ], g_al[(size_t)BATCH*SEQ*SEQ];

// ---------------------------------------------------------------------------
// bf16 helpers
// ---------------------------------------------------------------------------
__device__ __forceinline__ u16 f2bf(float x) {
    __nv_bfloat16 h = __float2bfloat16(x);
    return *reinterpret_cast<u16*>(&h);
}
__device__ __forceinline__ float bf2f(u16 u) {
    __nv_bfloat16 h = *reinterpret_cast<__nv_bfloat16*>(&u);
    return __bfloat162float(h);
}
__device__ __forceinline__ void split_bf16(float x, u16& hi, u16& lo) {
    hi = f2bf(x);
    lo = f2bf(x - bf2f(hi));
}
__device__ __forceinline__ unsigned pack2(u16 a, u16 b) {
    return (unsigned)a | ((unsigned)b << 16);
}

__device__ __forceinline__ void mma16816(float c[4],
                                         u32 a0, u32 a1, u32 a2, u32 a3,
                                         u32 b0, u32 b1)
{
    asm volatile(
        "mma.sync.aligned.m16n8k16.row.col.f32.bf16.bf16.f32 "
        "{%0,%1,%2,%3}, {%4,%5,%6,%7}, {%8,%9}, {%0,%1,%2,%3};\n"
        : "+f"(c[0]), "+f"(c[1]), "+f"(c[2]), "+f"(c[3])
        : "r"(a0), "r"(a1), "r"(a2), "r"(a3), "r"(b0), "r"(b1));
}

__device__ __forceinline__ void cp16(void* smem_dst, const void* gsrc) {
    u32 u = (u32)__cvta_generic_to_shared(smem_dst);
    asm volatile("cp.async.cg.shared.global [%0], [%1], 16;\n" :: "r"(u), "l"(gsrc));
}

__device__ __forceinline__ void ldsm4(u32& r0, u32& r1, u32& r2, u32& r3, u32 addr) {
    asm volatile("ldmatrix.sync.aligned.m8n8.x4.shared.b16 {%0,%1,%2,%3}, [%4];"
                 : "=r"(r0), "=r"(r1), "=r"(r2), "=r"(r3) : "r"(addr));
}

// ---------------------------------------------------------------------------
// Elementwise fp32 -> split bf16 (hi, lo)
// ---------------------------------------------------------------------------
__global__ __launch_bounds__(256)
void split_kernel(const float* __restrict__ x,
                  u16* __restrict__ hi, u16* __restrict__ lo, int n)
{
    int i = (blockIdx.x * blockDim.x + threadIdx.x) * 4;
    if (i >= n) return;
    float4 f = *reinterpret_cast<const float4*>(x + i);
    u16 h0,l0,h1,l1,h2,l2,h3,l3;
    split_bf16(f.x, h0, l0);
    split_bf16(f.y, h1, l1);
    split_bf16(f.z, h2, l2);
    split_bf16(f.w, h3, l3);
    *reinterpret_cast<uint2*>(hi + i) = make_uint2(pack2(h0,h1), pack2(h2,h3));
    *reinterpret_cast<uint2*>(lo + i) = make_uint2(pack2(l0,l1), pack2(l2,l3));
}

// ---------------------------------------------------------------------------
// Pipelined bf16 NT GEMM, 3-term hi/lo split, LDSM fragment loads:
//   C[m,n] = alpha * sum_k A[m,k]*B[n,k]  (+ bias[n])
// Block 128x128x32(bf16), 512 thr = 16 warps (4M x 4N), warp tile 32x32.
// 5-stage cp.async ring (200KB smem), SINGLE __syncthreads per iteration,
// loads for stage it+4 issued BEFORE the MMAs of stage it.
// EPI: 0 = fp32 C (alpha)  1 = split bf16 C (+bias)
//      2 = split bf16 C transposed per-batch [b][n][m] (+bias)
// ---------------------------------------------------------------------------
#define SMP   40                   // padded row stride (bf16): 80B, LDSM-conflict-free
#define ROWB  (SMP*2)              // 80 bytes
#define ARR_BYTES   (128*ROWB)     // 10240
#define STAGE_BYTES (4*ARR_BYTES)  // 40960
#define NSTAGE 5
#define DYNSMEM (NSTAGE*STAGE_BYTES)   // 204800

__device__ __forceinline__ void issue_stage(char* base,
    const u16* __restrict__ Agh, const u16* __restrict__ Agl,
    const u16* __restrict__ Bgh, const u16* __restrict__ Bgl,
    int row0, int col0, int K, int k0, int tid)
{
    // 512 threads, one 16B chunk per thread per array
    int r = tid >> 2;                // 0..127
    int c = (tid & 3) << 3;          // 0,8,16,24 (bf16 elems)
    size_t offA = (size_t)(row0 + r) * K + k0 + c;
    size_t offB = (size_t)(col0 + r) * K + k0 + c;
    int sm = r * ROWB + c * 2;
    cp16(base + sm,                 Agh + offA);
    cp16(base + ARR_BYTES   + sm,   Agl + offA);
    cp16(base + 2*ARR_BYTES + sm,   Bgh + offB);
    cp16(base + 3*ARR_BYTES + sm,   Bgl + offB);
}

template <int EPI>
__global__ __launch_bounds__(512)
void gemm_bf16(const u16* __restrict__ Agh, const u16* __restrict__ Agl,
               const u16* __restrict__ Bgh, const u16* __restrict__ Bgl,
               const float* __restrict__ bias,
               float* __restrict__ Cf,
               u16* __restrict__ Ch, u16* __restrict__ Cl,
               int M, int N, int K,
               long sA, long sB, long sC, float alpha)
{
    extern __shared__ char smem[];

    const int bz = blockIdx.z;
    Agh += (size_t)bz * sA;  Agl += (size_t)bz * sA;
    Bgh += (size_t)bz * sB;  Bgl += (size_t)bz * sB;

    const int tid  = threadIdx.x;
    const int lane = tid & 31;
    const int wid  = tid >> 5;          // 0..15
    const int g    = lane >> 2;
    const int tg   = lane & 3;
    const int wm0  = (wid & 3) * 32;    // 4 warps along M
    const int wn0  = (wid >> 2) * 32;   // 4 warps along N
    const int row0 = blockIdx.y * 128;
    const int col0 = blockIdx.x * 128;

    // LDSM lane offsets (bytes) within an array, at ks=0
    const u32 aLane = (u32)((wm0 + (lane & 15)) * ROWB + ((lane >> 4) << 4));
    const u32 bLane = (u32)((wn0 + ((lane >> 4) << 3) + (lane & 7)) * ROWB
                            + ((lane & 8) << 1));

    const u32 smem_base = (u32)__cvta_generic_to_shared(smem);

    float acc[2][4][4];
#pragma unroll
    for (int i = 0; i < 2; i++)
#pragma unroll
        for (int j = 0; j < 4; j++)
#pragma unroll
            for (int t = 0; t < 4; t++) acc[i][j][t] = 0.0f;

    const int NIT = K >> 5;

    // Prologue: issue stages 0 .. NSTAGE-2 (one group each)
#pragma unroll
    for (int s = 0; s < NSTAGE - 1; s++) {
        if (s < NIT)
            issue_stage(smem + s * STAGE_BYTES, Agh, Agl, Bgh, Bgl,
                        row0, col0, K, s << 5, tid);
        asm volatile("cp.async.commit_group;\n" ::: "memory");
    }

    for (int it = 0; it < NIT; it++) {
        // Stage `it` must be resident: allow the NSTAGE-2 newer groups pending.
        asm volatile("cp.async.wait_group %0;\n" :: "n"(NSTAGE - 2) : "memory");
        __syncthreads();   // all warps done reading buf (it-1)%NSTAGE

        // Issue loads for stage it+NSTAGE-1 into buf (it-1)%NSTAGE (now free)
        {
            int nx = it + NSTAGE - 1;
            if (nx < NIT)
                issue_stage(smem + (nx % NSTAGE) * STAGE_BYTES, Agh, Agl, Bgh, Bgl,
                            row0, col0, K, nx << 5, tid);
            asm volatile("cp.async.commit_group;\n" ::: "memory");
        }

        const u32 stg = smem_base + (u32)((it % NSTAGE) * STAGE_BYTES);

#pragma unroll
        for (int ks = 0; ks < 2; ks++) {
            const u32 ko = ks << 5;   // 16 bf16 = 32 bytes
            u32 ah[2][4], al[2][4];
#pragma unroll
            for (int i = 0; i < 2; i++) {
                u32 aoff = stg + aLane + (u32)(i * 16 * ROWB) + ko;
                ldsm4(ah[i][0], ah[i][1], ah[i][2], ah[i][3], aoff);
                ldsm4(al[i][0], al[i][1], al[i][2], al[i][3], aoff + ARR_BYTES);
            }
            u32 bh[4][2], bl[4][2];
#pragma unroll
            for (int p = 0; p < 2; p++) {
                u32 boff = stg + 2*ARR_BYTES + bLane + (u32)(p * 16 * ROWB) + ko;
                ldsm4(bh[2*p][0], bh[2*p][1], bh[2*p+1][0], bh[2*p+1][1], boff);
                ldsm4(bl[2*p][0], bl[2*p][1], bl[2*p+1][0], bl[2*p+1][1], boff + ARR_BYTES);
            }
#pragma unroll
            for (int j = 0; j < 4; j++) {
#pragma unroll
                for (int i = 0; i < 2; i++) {
                    mma16816(acc[i][j], ah[i][0], ah[i][1], ah[i][2], ah[i][3],
                             bh[j][0], bh[j][1]);
                    mma16816(acc[i][j], ah[i][0], ah[i][1], ah[i][2], ah[i][3],
                             bl[j][0], bl[j][1]);
                    mma16816(acc[i][j], al[i][0], al[i][1], al[i][2], al[i][3],
                             bh[j][0], bh[j][1]);
                }
            }
        }
        // no second sync: next iteration's top sync protects buffer reuse
    }

    // ---- Epilogue ----
#pragma unroll
    for (int i = 0; i < 2; i++) {
        int r1 = row0 + wm0 + 16 * i + g;
        int r2 = r1 + 8;
#pragma unroll
        for (int j = 0; j < 4; j++) {
            int n = col0 + wn0 + 8 * j + 2 * tg;
            float b0 = 0.0f, b1 = 0.0f;
            if (bias != nullptr) { b0 = bias[n]; b1 = bias[n + 1]; }
            float v00 = acc[i][j][0] * alpha + b0;
            float v01 = acc[i][j][1] * alpha + b1;
            float v10 = acc[i][j][2] * alpha + b0;
            float v11 = acc[i][j][3] * alpha + b1;

            if (EPI == 0) {
                float* Cb = Cf + (size_t)bz * sC;
                *reinterpret_cast<float2*>(Cb + (size_t)r1 * N + n) = make_float2(v00, v01);
                *reinterpret_cast<float2*>(Cb + (size_t)r2 * N + n) = make_float2(v10, v11);
            } else if (EPI == 1) {
                u16 h0,l0,h1,l1;
                split_bf16(v00, h0, l0); split_bf16(v01, h1, l1);
                *reinterpret_cast<u32*>(Ch + (size_t)r1 * N + n) = pack2(h0, h1);
                *reinterpret_cast<u32*>(Cl + (size_t)r1 * N + n) = pack2(l0, l1);
                split_bf16(v10, h0, l0); split_bf16(v11, h1, l1);
                *reinterpret_cast<u32*>(Ch + (size_t)r2 * N + n) = pack2(h0, h1);
                *reinterpret_cast<u32*>(Cl + (size_t)r2 * N + n) = pack2(l0, l1);
            } else {
                int   rr[2] = { r1, r2 };
                float vv[2][2] = { { v00, v01 }, { v10, v11 } };
#pragma unroll
                for (int t = 0; t < 2; t++) {
                    int m  = rr[t];
                    int b  = m >> 12;          // /SEQ
                    int mm = m & (SEQ - 1);
#pragma unroll
                    for (int u = 0; u < 2; u++) {
                        u16 h, l;
                        split_bf16(vv[t][u], h, l);
                        size_t idx = ((size_t)(b * DM + n + u)) * SEQ + mm;
                        Ch[idx] = h;
                        Cl[idx] = l;
                    }
                }
            }
        }
    }
}

// ---------------------------------------------------------------------------
// Row softmax: fp32 scores row -> split bf16 attention row
// ---------------------------------------------------------------------------
__global__ __launch_bounds__(256)
void softmax_split(const float* __restrict__ scores,
                   u16* __restrict__ ah, u16* __restrict__ al)
{
    const int S = SEQ;
    const size_t roff = (size_t)blockIdx.x * S;
    const float* p = scores + roff;
    const int tid = threadIdx.x;

    float v[16];
#pragma unroll
    for (int i = 0; i < 16; i++) v[i] = p[i * 256 + tid];

    float m = v[0];
#pragma unroll
    for (int i = 1; i < 16; i++) m = fmaxf(m, v[i]);

    __shared__ float red[32];
#pragma unroll
    for (int o = 16; o > 0; o >>= 1)
        m = fmaxf(m, __shfl_xor_sync(0xffffffffu, m, o));
    if ((tid & 31) == 0) red[tid >> 5] = m;
    __syncthreads();
    if (tid < 32) {
        float t = (tid < 8) ? red[tid] : -INFINITY;
#pragma unroll
        for (int o = 4; o > 0; o >>= 1)
            t = fmaxf(t, __shfl_xor_sync(0xffffffffu, t, o));
        if (tid == 0) red[0] = t;
    }
    __syncthreads();
    m = red[0];
    __syncthreads();

    float s = 0.0f;
#pragma unroll
    for (int i = 0; i < 16; i++) {
        v[i] = __expf(v[i] - m);
        s += v[i];
    }
#pragma unroll
    for (int o = 16; o > 0; o >>= 1)
        s += __shfl_xor_sync(0xffffffffu, s, o);
    if ((tid & 31) == 0) red[tid >> 5] = s;
    __syncthreads();
    if (tid < 32) {
        float t = (tid < 8) ? red[tid] : 0.0f;
#pragma unroll
        for (int o = 4; o > 0; o >>= 1)
            t += __shfl_xor_sync(0xffffffffu, t, o);
        if (tid == 0) red[0] = t;
    }
    __syncthreads();
    float inv = 1.0f / red[0];

#pragma unroll
    for (int i = 0; i < 16; i++) {
        float a = v[i] * inv;
        u16 h, l;
        split_bf16(a, h, l);
        ah[roff + i * 256 + tid] = h;
        al[roff + i * 256 + tid] = l;
    }
}

// ---------------------------------------------------------------------------
extern "C" void kernel_launch(void* const* d_in, const int* in_sizes, int n_in,
                              void* d_out, int out_size)
{
    const float* Q   = (const float*)d_in[0];
    const float* K   = (const float*)d_in[1];
    const float* V   = (const float*)d_in[2];
    const float* W_q = (const float*)d_in[3];
    const float* b_q = (const float*)d_in[4];
    const float* W_k = (const float*)d_in[5];
    const float* b_k = (const float*)d_in[6];
    const float* W_v = (const float*)d_in[7];
    const float* b_v = (const float*)d_in[8];
    float* out = (float*)d_out;

    u16 *Qh,*Ql,*Kh,*Kl,*Vh,*Vl, *Wqh,*Wql,*Wkh,*Wkl,*Wvh,*Wvl;
    u16 *qh,*ql,*kh,*kl,*vth,*vtl,*ah,*al;
    float* s;
    cudaGetSymbolAddress((void**)&Qh, g_Qh);   cudaGetSymbolAddress((void**)&Ql, g_Ql);
    cudaGetSymbolAddress((void**)&Kh, g_Kh);   cudaGetSymbolAddress((void**)&Kl, g_Kl);
    cudaGetSymbolAddress((void**)&Vh, g_Vh);   cudaGetSymbolAddress((void**)&Vl, g_Vl);
    cudaGetSymbolAddress((void**)&Wqh, g_Wqh); cudaGetSymbolAddress((void**)&Wql, g_Wql);
    cudaGetSymbolAddress((void**)&Wkh, g_Wkh); cudaGetSymbolAddress((void**)&Wkl, g_Wkl);
    cudaGetSymbolAddress((void**)&Wvh, g_Wvh); cudaGetSymbolAddress((void**)&Wvl, g_Wvl);
    cudaGetSymbolAddress((void**)&qh, g_qh);   cudaGetSymbolAddress((void**)&ql, g_ql);
    cudaGetSymbolAddress((void**)&kh, g_kh);   cudaGetSymbolAddress((void**)&kl, g_kl);
    cudaGetSymbolAddress((void**)&vth, g_vth); cudaGetSymbolAddress((void**)&vtl, g_vtl);
    cudaGetSymbolAddress((void**)&ah, g_ah);   cudaGetSymbolAddress((void**)&al, g_al);
    cudaGetSymbolAddress((void**)&s, g_s);

    cudaFuncSetAttribute(gemm_bf16<0>, cudaFuncAttributeMaxDynamicSharedMemorySize, DYNSMEM);
    cudaFuncSetAttribute(gemm_bf16<1>, cudaFuncAttributeMaxDynamicSharedMemorySize, DYNSMEM);
    cudaFuncSetAttribute(gemm_bf16<2>, cudaFuncAttributeMaxDynamicSharedMemorySize, DYNSMEM);

    const float scale = 1.0f / sqrtf((float)DM);
    dim3 blk(512);

    const int n1 = ROWS * DM;
    const int n2 = DM * DM;
    split_kernel<<<n1/1024, 256>>>(Q, Qh, Ql, n1);
    split_kernel<<<n1/1024, 256>>>(K, Kh, Kl, n1);
    split_kernel<<<n1/1024, 256>>>(V, Vh, Vl, n1);
    split_kernel<<<n2/1024, 256>>>(W_q, Wqh, Wql, n2);
    split_kernel<<<n2/1024, 256>>>(W_k, Wkh, Wkl, n2);
    split_kernel<<<n2/1024, 256>>>(W_v, Wvh, Wvl, n2);

    // Projections (NT): [8192,512] = X @ W^T + b ; q,k -> split ; v -> split+T
    {
        dim3 gp(DM/128, ROWS/128, 1);
        gemm_bf16<1><<<gp, blk, DYNSMEM>>>(Qh, Ql, Wqh, Wql, b_q,
            nullptr, qh, ql, ROWS, DM, DM, 0, 0, 0, 1.0f);
        gemm_bf16<1><<<gp, blk, DYNSMEM>>>(Kh, Kl, Wkh, Wkl, b_k,
            nullptr, kh, kl, ROWS, DM, DM, 0, 0, 0, 1.0f);
        gemm_bf16<2><<<gp, blk, DYNSMEM>>>(Vh, Vl, Wvh, Wvl, b_v,
            nullptr, vth, vtl, ROWS, DM, DM, 0, 0, 0, 1.0f);
    }

    // Scores (NT, per batch): s = scale * q @ k^T, M=N=4096, K=512
    {
        dim3 gs(SEQ/128, SEQ/128, BATCH);
        gemm_bf16<0><<<gs, blk, DYNSMEM>>>(qh, ql, kh, kl, nullptr,
            s, nullptr, nullptr, SEQ, SEQ, DM,
            (long)SEQ*DM, (long)SEQ*DM, (long)SEQ*SEQ, scale);
    }

    // Softmax -> split bf16 attention
    softmax_split<<<ROWS, 256>>>(s, ah, al);

    // Output (NT, per batch): out = attn @ v via vT, M=4096, N=512, K=4096
    {
        dim3 go(DM/128, SEQ/128, BATCH);
        gemm_bf16<0><<<go, blk, DYNSMEM>>>(ah, al, vth, vtl, nullptr,
            out, nullptr, nullptr, SEQ, DM, SEQ,
            (long)SEQ*SEQ, (long)DM*SEQ, (long)SEQ*DM, 1.0f);
    }
}

// round 8
// speedup vs baseline: 1.0981x; 1.0981x over previous
#include <cuda_runtime.h>
#include <cuda_bf16.h>
#include <math.h>

#define BATCH 2
#define SEQ   4096
#define DM    512
#define ROWS  (BATCH*SEQ)   // 8192

typedef unsigned short u16;
typedef unsigned int   u32;

// ---------------------------------------------------------------------------
// Device scratch (allocation-free rule: __device__ globals)
// ---------------------------------------------------------------------------
__device__ u16 g_Qh[(size_t)ROWS*DM], g_Ql[(size_t)ROWS*DM];
__device__ u16 g_Kh[(size_t)ROWS*DM], g_Kl[(size_t)ROWS*DM];
__device__ u16 g_Vh[(size_t)ROWS*DM], g_Vl[(size_t)ROWS*DM];
__device__ u16 g_Wqh[DM*DM], g_Wql[DM*DM];
__device__ u16 g_Wkh[DM*DM], g_Wkl[DM*DM];
__device__ u16 g_Wvh[DM*DM], g_Wvl[DM*DM];
__device__ u16 g_qh[(size_t)ROWS*DM], g_ql[(size_t)ROWS*DM];
__device__ u16 g_kh[(size_t)ROWS*DM], g_kl[(size_t)ROWS*DM];
__device__ u16 g_vth[(size_t)BATCH*DM*SEQ], g_vtl[(size_t)BATCH*DM*SEQ];
__device__ float g_s[(size_t)BATCH*SEQ*SEQ];
__device__ u16 g_ah[(size_t)BATCH*SEQ*SEQ], g_al[(size_t)BATCH*SEQ*SEQ];

// ---------------------------------------------------------------------------
// bf16 helpers
// ---------------------------------------------------------------------------
__device__ __forceinline__ u16 f2bf(float x) {
    __nv_bfloat16 h = __float2bfloat16(x);
    return *reinterpret_cast<u16*>(&h);
}
__device__ __forceinline__ float bf2f(u16 u) {
    __nv_bfloat16 h = *reinterpret_cast<__nv_bfloat16*>(&u);
    return __bfloat162float(h);
}
__device__ __forceinline__ void split_bf16(float x, u16& hi, u16& lo) {
    hi = f2bf(x);
    lo = f2bf(x - bf2f(hi));
}
__device__ __forceinline__ unsigned pack2(u16 a, u16 b) {
    return (unsigned)a | ((unsigned)b << 16);
}

__device__ __forceinline__ void mma16816(float c[4],
                                         u32 a0, u32 a1, u32 a2, u32 a3,
                                         u32 b0, u32 b1)
{
    asm volatile(
        "mma.sync.aligned.m16n8k16.row.col.f32.bf16.bf16.f32 "
        "{%0,%1,%2,%3}, {%4,%5,%6,%7}, {%8,%9}, {%0,%1,%2,%3};\n"
        : "+f"(c[0]), "+f"(c[1]), "+f"(c[2]), "+f"(c[3])
        : "r"(a0), "r"(a1), "r"(a2), "r"(a3), "r"(b0), "r"(b1));
}

__device__ __forceinline__ void cp16(void* smem_dst, const void* gsrc) {
    u32 u = (u32)__cvta_generic_to_shared(smem_dst);
    asm volatile("cp.async.cg.shared.global [%0], [%1], 16;\n" :: "r"(u), "l"(gsrc));
}

__device__ __forceinline__ void ldsm4(u32& r0, u32& r1, u32& r2, u32& r3, u32 addr) {
    asm volatile("ldmatrix.sync.aligned.m8n8.x4.shared.b16 {%0,%1,%2,%3}, [%4];"
                 : "=r"(r0), "=r"(r1), "=r"(r2), "=r"(r3) : "r"(addr));
}

// ---------------------------------------------------------------------------
// Fused fp32 -> split bf16 for 3 equal-size arrays (1 launch instead of 3)
// ---------------------------------------------------------------------------
__global__ __launch_bounds__(256)
void split3_kernel(const float* __restrict__ x0, const float* __restrict__ x1,
                   const float* __restrict__ x2,
                   u16* __restrict__ h0a, u16* __restrict__ l0a,
                   u16* __restrict__ h1a, u16* __restrict__ l1a,
                   u16* __restrict__ h2a, u16* __restrict__ l2a, int n)
{
    const float* x;
    u16 *hp, *lp;
    if (blockIdx.y == 0)      { x = x0; hp = h0a; lp = l0a; }
    else if (blockIdx.y == 1) { x = x1; hp = h1a; lp = l1a; }
    else                      { x = x2; hp = h2a; lp = l2a; }

    int i = (blockIdx.x * blockDim.x + threadIdx.x) * 4;
    if (i >= n) return;
    float4 f = *reinterpret_cast<const float4*>(x + i);
    u16 h0,l0,h1,l1,h2,l2,h3,l3;
    split_bf16(f.x, h0, l0);
    split_bf16(f.y, h1, l1);
    split_bf16(f.z, h2, l2);
    split_bf16(f.w, h3, l3);
    *reinterpret_cast<uint2*>(hp + i) = make_uint2(pack2(h0,h1), pack2(h2,h3));
    *reinterpret_cast<uint2*>(lp + i) = make_uint2(pack2(l0,l1), pack2(l2,l3));
}

// ---------------------------------------------------------------------------
// Pipelined bf16 NT GEMM, 3-term hi/lo split, LDSM fragment loads:
//   C[m,n] = alpha * sum_k A[m,k]*B[n,k]  (+ bias[n])
// Block 128x128x32(bf16), 256 thr = 8 warps (4M x 2N), warp tile 32x64.
// 2-stage cp.async ring (80KB smem) -> 2 CTAs/SM for cross-CTA stall overlap.
// Term-major MMA order (hh, hl, lh) to break accumulator RAW chains.
// EPI: 0 = fp32 C (alpha)  1 = split bf16 C (+bias)
//      2 = split bf16 C transposed per-batch [b][n][m] (+bias)
// ---------------------------------------------------------------------------
#define SMP   40                   // padded row stride (bf16): 80B, LDSM-conflict-free
#define ROWB  (SMP*2)              // 80 bytes
#define ARR_BYTES   (128*ROWB)     // 10240
#define STAGE_BYTES (4*ARR_BYTES)  // 40960
#define NSTAGE 2
#define DYNSMEM (NSTAGE*STAGE_BYTES)   // 81920 -> 2 CTAs/SM

__device__ __forceinline__ void issue_stage(char* base,
    const u16* __restrict__ Agh, const u16* __restrict__ Agl,
    const u16* __restrict__ Bgh, const u16* __restrict__ Bgl,
    int row0, int col0, int K, int k0, int tid)
{
#pragma unroll
    for (int e = 0; e < 2; e++) {
        int idx = tid + (e << 8);        // 0..511
        int r = idx >> 2;                // 0..127
        int c = (idx & 3) << 3;          // 0,8,16,24 (bf16 elems)
        size_t offA = (size_t)(row0 + r) * K + k0 + c;
        size_t offB = (size_t)(col0 + r) * K + k0 + c;
        int sm = r * ROWB + c * 2;
        cp16(base + sm,                 Agh + offA);
        cp16(base + ARR_BYTES   + sm,   Agl + offA);
        cp16(base + 2*ARR_BYTES + sm,   Bgh + offB);
        cp16(base + 3*ARR_BYTES + sm,   Bgl + offB);
    }
}

template <int EPI>
__global__ __launch_bounds__(256, 2)
void gemm_bf16(const u16* __restrict__ Agh, const u16* __restrict__ Agl,
               const u16* __restrict__ Bgh, const u16* __restrict__ Bgl,
               const float* __restrict__ bias,
               float* __restrict__ Cf,
               u16* __restrict__ Ch, u16* __restrict__ Cl,
               int M, int N, int K,
               long sA, long sB, long sC, float alpha)
{
    extern __shared__ char smem[];

    const int bz = blockIdx.z;
    Agh += (size_t)bz * sA;  Agl += (size_t)bz * sA;
    Bgh += (size_t)bz * sB;  Bgl += (size_t)bz * sB;

    const int tid  = threadIdx.x;
    const int lane = tid & 31;
    const int wid  = tid >> 5;          // 0..7
    const int g    = lane >> 2;
    const int tg   = lane & 3;
    const int wm0  = (wid & 3) * 32;    // 4 warps along M
    const int wn0  = (wid >> 2) * 64;   // 2 warps along N
    const int row0 = blockIdx.y * 128;
    const int col0 = blockIdx.x * 128;

    // LDSM lane offsets (bytes) within an array, at ks=0
    const u32 aLane = (u32)((wm0 + (lane & 15)) * ROWB + ((lane >> 4) << 4));
    const u32 bLane = (u32)((wn0 + ((lane >> 4) << 3) + (lane & 7)) * ROWB
                            + ((lane & 8) << 1));

    const u32 smem_base = (u32)__cvta_generic_to_shared(smem);

    float acc[2][8][4];
#pragma unroll
    for (int i = 0; i < 2; i++)
#pragma unroll
        for (int j = 0; j < 8; j++)
#pragma unroll
            for (int t = 0; t < 4; t++) acc[i][j][t] = 0.0f;

    const int NIT = K >> 5;

#pragma unroll
    for (int s = 0; s < NSTAGE; s++) {
        issue_stage(smem + s * STAGE_BYTES, Agh, Agl, Bgh, Bgl,
                    row0, col0, K, s << 5, tid);
        asm volatile("cp.async.commit_group;\n" ::: "memory");
    }

    for (int it = 0; it < NIT; it++) {
        asm volatile("cp.async.wait_group 1;\n" ::: "memory");
        __syncthreads();

        const u32 stg = smem_base + (u32)((it & 1) * STAGE_BYTES);

#pragma unroll
        for (int ks = 0; ks < 2; ks++) {
            const u32 ko = ks << 5;   // 16 bf16 = 32 bytes
            u32 ah[2][4], al[2][4];
#pragma unroll
            for (int i = 0; i < 2; i++) {
                u32 aoff = stg + aLane + (u32)(i * 16 * ROWB) + ko;
                ldsm4(ah[i][0], ah[i][1], ah[i][2], ah[i][3], aoff);
                ldsm4(al[i][0], al[i][1], al[i][2], al[i][3], aoff + ARR_BYTES);
            }
            // process 8 N-sites in two halves of 4 to bound register pressure
#pragma unroll
            for (int half = 0; half < 2; half++) {
                u32 bh[4][2], bl[4][2];
#pragma unroll
                for (int p = 0; p < 2; p++) {
                    u32 boff = stg + 2*ARR_BYTES + bLane
                             + (u32)((half * 2 + p) * 16 * ROWB) + ko;
                    ldsm4(bh[2*p][0], bh[2*p][1], bh[2*p+1][0], bh[2*p+1][1], boff);
                    ldsm4(bl[2*p][0], bl[2*p][1], bl[2*p+1][0], bl[2*p+1][1],
                          boff + ARR_BYTES);
                }
                // term-major: consecutive MMAs to same acc are 8 apart
#pragma unroll
                for (int i = 0; i < 2; i++)
#pragma unroll
                    for (int j = 0; j < 4; j++)
                        mma16816(acc[i][half*4 + j],
                                 ah[i][0], ah[i][1], ah[i][2], ah[i][3],
                                 bh[j][0], bh[j][1]);
#pragma unroll
                for (int i = 0; i < 2; i++)
#pragma unroll
                    for (int j = 0; j < 4; j++)
                        mma16816(acc[i][half*4 + j],
                                 ah[i][0], ah[i][1], ah[i][2], ah[i][3],
                                 bl[j][0], bl[j][1]);
#pragma unroll
                for (int i = 0; i < 2; i++)
#pragma unroll
                    for (int j = 0; j < 4; j++)
                        mma16816(acc[i][half*4 + j],
                                 al[i][0], al[i][1], al[i][2], al[i][3],
                                 bh[j][0], bh[j][1]);
            }
        }
        __syncthreads();

        if (it + NSTAGE < NIT)
            issue_stage(smem + (it & 1) * STAGE_BYTES, Agh, Agl, Bgh, Bgl,
                        row0, col0, K, (it + NSTAGE) << 5, tid);
        asm volatile("cp.async.commit_group;\n" ::: "memory");
    }

    // ---- Epilogue ----
#pragma unroll
    for (int i = 0; i < 2; i++) {
        int r1 = row0 + wm0 + 16 * i + g;
        int r2 = r1 + 8;
#pragma unroll
        for (int j = 0; j < 8; j++) {
            int n = col0 + wn0 + 8 * j + 2 * tg;
            float b0 = 0.0f, b1 = 0.0f;
            if (bias != nullptr) { b0 = bias[n]; b1 = bias[n + 1]; }
            float v00 = acc[i][j][0] * alpha + b0;
            float v01 = acc[i][j][1] * alpha + b1;
            float v10 = acc[i][j][2] * alpha + b0;
            float v11 = acc[i][j][3] * alpha + b1;

            if (EPI == 0) {
                float* Cb = Cf + (size_t)bz * sC;
                *reinterpret_cast<float2*>(Cb + (size_t)r1 * N + n) = make_float2(v00, v01);
                *reinterpret_cast<float2*>(Cb + (size_t)r2 * N + n) = make_float2(v10, v11);
            } else if (EPI == 1) {
                u16 h0,l0,h1,l1;
                split_bf16(v00, h0, l0); split_bf16(v01, h1, l1);
                *reinterpret_cast<u32*>(Ch + (size_t)r1 * N + n) = pack2(h0, h1);
                *reinterpret_cast<u32*>(Cl + (size_t)r1 * N + n) = pack2(l0, l1);
                split_bf16(v10, h0, l0); split_bf16(v11, h1, l1);
                *reinterpret_cast<u32*>(Ch + (size_t)r2 * N + n) = pack2(h0, h1);
                *reinterpret_cast<u32*>(Cl + (size_t)r2 * N + n) = pack2(l0, l1);
            } else {
                int   rr[2] = { r1, r2 };
                float vv[2][2] = { { v00, v01 }, { v10, v11 } };
#pragma unroll
                for (int t = 0; t < 2; t++) {
                    int m  = rr[t];
                    int b  = m >> 12;          // /SEQ
                    int mm = m & (SEQ - 1);
#pragma unroll
                    for (int u = 0; u < 2; u++) {
                        u16 h, l;
                        split_bf16(vv[t][u], h, l);
                        size_t idx = ((size_t)(b * DM + n + u)) * SEQ + mm;
                        Ch[idx] = h;
                        Cl[idx] = l;
                    }
                }
            }
        }
    }
}

// ---------------------------------------------------------------------------
// Row softmax: fp32 scores row -> split bf16 attention row
// ---------------------------------------------------------------------------
__global__ __launch_bounds__(256)
void softmax_split(const float* __restrict__ scores,
                   u16* __restrict__ ah, u16* __restrict__ al)
{
    const int S = SEQ;
    const size_t roff = (size_t)blockIdx.x * S;
    const float* p = scores + roff;
    const int tid = threadIdx.x;

    float v[16];
#pragma unroll
    for (int i = 0; i < 16; i++) v[i] = p[i * 256 + tid];

    float m = v[0];
#pragma unroll
    for (int i = 1; i < 16; i++) m = fmaxf(m, v[i]);

    __shared__ float red[32];
#pragma unroll
    for (int o = 16; o > 0; o >>= 1)
        m = fmaxf(m, __shfl_xor_sync(0xffffffffu, m, o));
    if ((tid & 31) == 0) red[tid >> 5] = m;
    __syncthreads();
    if (tid < 32) {
        float t = (tid < 8) ? red[tid] : -INFINITY;
#pragma unroll
        for (int o = 4; o > 0; o >>= 1)
            t = fmaxf(t, __shfl_xor_sync(0xffffffffu, t, o));
        if (tid == 0) red[0] = t;
    }
    __syncthreads();
    m = red[0];
    __syncthreads();

    float s = 0.0f;
#pragma unroll
    for (int i = 0; i < 16; i++) {
        v[i] = __expf(v[i] - m);
        s += v[i];
    }
#pragma unroll
    for (int o = 16; o > 0; o >>= 1)
        s += __shfl_xor_sync(0xffffffffu, s, o);
    if ((tid & 31) == 0) red[tid >> 5] = s;
    __syncthreads();
    if (tid < 32) {
        float t = (tid < 8) ? red[tid] : 0.0f;
#pragma unroll
        for (int o = 4; o > 0; o >>= 1)
            t += __shfl_xor_sync(0xffffffffu, t, o);
        if (tid == 0) red[0] = t;
    }
    __syncthreads();
    float inv = 1.0f / red[0];

#pragma unroll
    for (int i = 0; i < 16; i++) {
        float a = v[i] * inv;
        u16 h, l;
        split_bf16(a, h, l);
        ah[roff + i * 256 + tid] = h;
        al[roff + i * 256 + tid] = l;
    }
}

// ---------------------------------------------------------------------------
extern "C" void kernel_launch(void* const* d_in, const int* in_sizes, int n_in,
                              void* d_out, int out_size)
{
    const float* Q   = (const float*)d_in[0];
    const float* K   = (const float*)d_in[1];
    const float* V   = (const float*)d_in[2];
    const float* W_q = (const float*)d_in[3];
    const float* b_q = (const float*)d_in[4];
    const float* W_k = (const float*)d_in[5];
    const float* b_k = (const float*)d_in[6];
    const float* W_v = (const float*)d_in[7];
    const float* b_v = (const float*)d_in[8];
    float* out = (float*)d_out;

    u16 *Qh,*Ql,*Kh,*Kl,*Vh,*Vl, *Wqh,*Wql,*Wkh,*Wkl,*Wvh,*Wvl;
    u16 *qh,*ql,*kh,*kl,*vth,*vtl,*ah,*al;
    float* s;
    cudaGetSymbolAddress((void**)&Qh, g_Qh);   cudaGetSymbolAddress((void**)&Ql, g_Ql);
    cudaGetSymbolAddress((void**)&Kh, g_Kh);   cudaGetSymbolAddress((void**)&Kl, g_Kl);
    cudaGetSymbolAddress((void**)&Vh, g_Vh);   cudaGetSymbolAddress((void**)&Vl, g_Vl);
    cudaGetSymbolAddress((void**)&Wqh, g_Wqh); cudaGetSymbolAddress((void**)&Wql, g_Wql);
    cudaGetSymbolAddress((void**)&Wkh, g_Wkh); cudaGetSymbolAddress((void**)&Wkl, g_Wkl);
    cudaGetSymbolAddress((void**)&Wvh, g_Wvh); cudaGetSymbolAddress((void**)&Wvl, g_Wvl);
    cudaGetSymbolAddress((void**)&qh, g_qh);   cudaGetSymbolAddress((void**)&ql, g_ql);
    cudaGetSymbolAddress((void**)&kh, g_kh);   cudaGetSymbolAddress((void**)&kl, g_kl);
    cudaGetSymbolAddress((void**)&vth, g_vth); cudaGetSymbolAddress((void**)&vtl, g_vtl);
    cudaGetSymbolAddress((void**)&ah, g_ah);   cudaGetSymbolAddress((void**)&al, g_al);
    cudaGetSymbolAddress((void**)&s, g_s);

    cudaFuncSetAttribute(gemm_bf16<0>, cudaFuncAttributeMaxDynamicSharedMemorySize, DYNSMEM);
    cudaFuncSetAttribute(gemm_bf16<1>, cudaFuncAttributeMaxDynamicSharedMemorySize, DYNSMEM);
    cudaFuncSetAttribute(gemm_bf16<2>, cudaFuncAttributeMaxDynamicSharedMemorySize, DYNSMEM);

    const float scale = 1.0f / sqrtf((float)DM);
    dim3 blk(256);

    const int n1 = ROWS * DM;
    const int n2 = DM * DM;
    // 2 fused split launches (keeps ncu -s 5 on the scores GEMM)
    split3_kernel<<<dim3(n1/1024, 3), blk>>>(Q, K, V,
        Qh, Ql, Kh, Kl, Vh, Vl, n1);
    split3_kernel<<<dim3(n2/1024, 3), blk>>>(W_q, W_k, W_v,
        Wqh, Wql, Wkh, Wkl, Wvh, Wvl, n2);

    // Projections (NT): [8192,512] = X @ W^T + b ; q,k -> split ; v -> split+T
    {
        dim3 gp(DM/128, ROWS/128, 1);
        gemm_bf16<1><<<gp, blk, DYNSMEM>>>(Qh, Ql, Wqh, Wql, b_q,
            nullptr, qh, ql, ROWS, DM, DM, 0, 0, 0, 1.0f);
        gemm_bf16<1><<<gp, blk, DYNSMEM>>>(Kh, Kl, Wkh, Wkl, b_k,
            nullptr, kh, kl, ROWS, DM, DM, 0, 0, 0, 1.0f);
        gemm_bf16<2><<<gp, blk, DYNSMEM>>>(Vh, Vl, Wvh, Wvl, b_v,
            nullptr, vth, vtl, ROWS, DM, DM, 0, 0, 0, 1.0f);
    }

    // Scores (NT, per batch): s = scale * q @ k^T, M=N=4096, K=512  [launch #5]
    {
        dim3 gs(SEQ/128, SEQ/128, BATCH);
        gemm_bf16<0><<<gs, blk, DYNSMEM>>>(qh, ql, kh, kl, nullptr,
            s, nullptr, nullptr, SEQ, SEQ, DM,
            (long)SEQ*DM, (long)SEQ*DM, (long)SEQ*SEQ, scale);
    }

    // Softmax -> split bf16 attention
    softmax_split<<<ROWS, blk>>>(s, ah, al);

    // Output (NT, per batch): out = attn @ v via vT, M=4096, N=512, K=4096
    {
        dim3 go(DM/128, SEQ/128, BATCH);
        gemm_bf16<0><<<go, blk, DYNSMEM>>>(ah, al, vth, vtl, nullptr,
            out, nullptr, nullptr, SEQ, DM, SEQ,
            (long)SEQ*SEQ, (long)DM*SEQ, (long)SEQ*DM, 1.0f);
    }
}